// round 14
// baseline (speedup 1.0000x reference)
#include <cuda_runtime.h>
#include <math.h>
#include <stdint.h>

#define B_ 64
#define T_ 1024
#define H_ 256
#define M_ (B_*T_)   /* 65536 rows for the projection GEMMs */

// Scratch (device globals — no runtime allocation allowed)
__device__ float g_xp[B_*T_*H_];   // input-projection result for current layer
__device__ float g_h [B_*T_*H_];   // layer-0 hidden sequence

// ---------------------------------------------------------------------------
// packed f32x2 helpers (sm_100+): one instr = 2 fp32 FMAs
// ---------------------------------------------------------------------------
__device__ __forceinline__ unsigned long long ffma2(unsigned long long a,
                                                    unsigned long long b,
                                                    unsigned long long c) {
    unsigned long long d;
    asm("fma.rn.f32x2 %0, %1, %2, %3;" : "=l"(d) : "l"(a), "l"(b), "l"(c));
    return d;
}
__device__ __forceinline__ unsigned long long pack2(float lo, float hi) {
    unsigned long long r;
    asm("mov.b64 %0, {%1, %2};"
        : "=l"(r) : "r"(__float_as_uint(lo)), "r"(__float_as_uint(hi)));
    return r;
}
__device__ __forceinline__ float2 unpack2(unsigned long long v) {
    uint32_t lo, hi;
    asm("mov.b64 {%0, %1}, %2;" : "=r"(lo), "=r"(hi) : "l"(v));
    return make_float2(__uint_as_float(lo), __uint_as_float(hi));
}
__device__ __forceinline__ uint32_t smem_u32(const void* p) {
    return (uint32_t)__cvta_generic_to_shared(p);
}
// Fast accurate-enough tanh: ~1e-7 rel err, MUFU-based (no branches).
__device__ __forceinline__ float tanh_fast(float x) {
    float xc = fminf(fmaxf(x, -9.0f), 9.0f);     // tanh(9)=1-3e-8
    float e  = __expf(2.0f * xc);
    return __fdividef(e - 1.0f, e + 1.0f);
}

// ---------------------------------------------------------------------------
// Projection GEMM: out[M,256] = A[M,256] @ W[256,256]^T + bias
// (unchanged: ~214us each)
// ---------------------------------------------------------------------------
__global__ void __launch_bounds__(256, 2)
gemm_bias(const float* __restrict__ A, const float* __restrict__ W,
          const float* __restrict__ bias, float* __restrict__ out)
{
    __shared__ __align__(16) float As[16][128];
    __shared__ __align__(16) float Bs[16][64];

    const int tid = threadIdx.x;
    const int m0  = blockIdx.x * 128;
    const int n0  = blockIdx.y * 64;
    const int tx  = tid & 15;
    const int ty  = tid >> 4;
    const int lm  = tid >> 1;
    const int ak  = (tid & 1) * 8;
    const int ln  = tid & 63;
    const int bk  = (tid >> 6) * 4;

    unsigned long long acc[4][4];
#pragma unroll
    for (int p = 0; p < 4; p++)
#pragma unroll
        for (int n = 0; n < 4; n++) acc[p][n] = 0ull;

    const float* Arow = A + (size_t)(m0 + lm) * H_;
    const float* Wrow = W + (size_t)(n0 + ln) * H_;

    for (int k0 = 0; k0 < H_; k0 += 16) {
        float4 av0 = *(const float4*)(Arow + k0 + ak);
        float4 av1 = *(const float4*)(Arow + k0 + ak + 4);
        float4 bv0 = *(const float4*)(Wrow + k0 + bk);
        As[ak+0][lm] = av0.x; As[ak+1][lm] = av0.y;
        As[ak+2][lm] = av0.z; As[ak+3][lm] = av0.w;
        As[ak+4][lm] = av1.x; As[ak+5][lm] = av1.y;
        As[ak+6][lm] = av1.z; As[ak+7][lm] = av1.w;
        Bs[bk+0][ln] = bv0.x; Bs[bk+1][ln] = bv0.y;
        Bs[bk+2][ln] = bv0.z; Bs[bk+3][ln] = bv0.w;
        __syncthreads();
#pragma unroll
        for (int k = 0; k < 16; k++) {
            const ulonglong2* ap = (const ulonglong2*)&As[k][ty * 8];
            ulonglong2 q0 = ap[0];
            ulonglong2 q1 = ap[1];
            float4 bv = *(const float4*)&Bs[k][tx * 4];
            unsigned long long b0 = pack2(bv.x, bv.x);
            unsigned long long b1 = pack2(bv.y, bv.y);
            unsigned long long b2 = pack2(bv.z, bv.z);
            unsigned long long b3 = pack2(bv.w, bv.w);
            acc[0][0]=ffma2(q0.x,b0,acc[0][0]); acc[0][1]=ffma2(q0.x,b1,acc[0][1]);
            acc[0][2]=ffma2(q0.x,b2,acc[0][2]); acc[0][3]=ffma2(q0.x,b3,acc[0][3]);
            acc[1][0]=ffma2(q0.y,b0,acc[1][0]); acc[1][1]=ffma2(q0.y,b1,acc[1][1]);
            acc[1][2]=ffma2(q0.y,b2,acc[1][2]); acc[1][3]=ffma2(q0.y,b3,acc[1][3]);
            acc[2][0]=ffma2(q1.x,b0,acc[2][0]); acc[2][1]=ffma2(q1.x,b1,acc[2][1]);
            acc[2][2]=ffma2(q1.x,b2,acc[2][2]); acc[2][3]=ffma2(q1.x,b3,acc[2][3]);
            acc[3][0]=ffma2(q1.y,b0,acc[3][0]); acc[3][1]=ffma2(q1.y,b1,acc[3][1]);
            acc[3][2]=ffma2(q1.y,b2,acc[3][2]); acc[3][3]=ffma2(q1.y,b3,acc[3][3]);
        }
        __syncthreads();
    }

    float4 bb = *(const float4*)(bias + n0 + tx * 4);
#pragma unroll
    for (int p = 0; p < 4; p++) {
        float2 c0 = unpack2(acc[p][0]);
        float2 c1 = unpack2(acc[p][1]);
        float2 c2 = unpack2(acc[p][2]);
        float2 c3 = unpack2(acc[p][3]);
        float4 lo = make_float4(c0.x + bb.x, c1.x + bb.y, c2.x + bb.z, c3.x + bb.w);
        float4 hi = make_float4(c0.y + bb.x, c1.y + bb.y, c2.y + bb.z, c3.y + bb.w);
        size_t r = (size_t)(m0 + ty * 8 + 2 * p) * H_ + n0 + tx * 4;
        *(float4*)(out + r)      = lo;
        *(float4*)(out + r + H_) = hi;
    }
}

// ---------------------------------------------------------------------------
// Recurrent scan, round 14: 512 threads/CTA + tagged-word polling.
//  Rounds 6-13 proved the handshake primitive is minor; the big term is
//  compute LATENCY at 2 warps/SMSP. Fix: k-quarter split at 512 threads —
//  thread t computes output j=t>>1 over k-quarter kq=t&1 (64-wide dot,
//  w = 64 regs), giving 4 warps/SMSP and 32-FFMA2 chains. NB=1, grid=128
//  (the proven operating point). shfl.xor(1) combines quarters; kq=0 lanes
//  run the round-13 single-8B (value,tag) exchange:
//   - sender: st.shared::cluster.b64 of packed (partial, tag=t+1) — aligned
//     b64 is single-copy atomic, flag IS the data word.
//   - receiver: ld.volatile.shared.v2.u32 spin until tag==t+1.
//   - slot reuse (t+2) fenced by the per-step __syncthreads chain.
//  h segments at 68-float stride: kq0/kq1 LDS.128 broadcast groups hit
//  disjoint bank quads -> single-phase.
// ---------------------------------------------------------------------------
__global__ void __launch_bounds__(512, 1) __cluster_dims__(2, 1, 1)
elman_scan(const float* __restrict__ xp, const float* __restrict__ Whh,
           float* __restrict__ ys)
{
    __shared__ __align__(16) float hs[2][2][68];            // [buf][kq][64+4]
    __shared__ __align__(16) unsigned long long pbt[2][128];// (val,tag) slots

    const int tid  = threadIdx.x;
    const int rank = (int)(blockIdx.x & 1);
    const int batch= (int)(blockIdx.x >> 1);
    const int kq   = tid & 1;          // k-quarter within the local half
    const int j    = tid >> 1;         // output index [0,256)
    const int jl   = j & 127;          // index within j's half
    const bool mine = ((tid >> 8) == rank);   // warps owning local outputs

    // Weights: W_hh[j][rank*128 + kq*64 .. +63] as 32 packed f32x2 (64 regs)
    unsigned long long w[32];
    {
        const ulonglong2* wv = (const ulonglong2*)
            (Whh + (size_t)j * H_ + rank * 128 + kq * 64);
#pragma unroll
        for (int i = 0; i < 16; i++) {
            ulonglong2 v = wv[i];
            w[2*i] = v.x; w[2*i+1] = v.y;
        }
    }

    for (int i = tid; i < 2 * 2 * 68; i += 512) (&hs[0][0][0])[i] = 0.0f;
    if (tid < 256) pbt[tid >> 7][tid & 127] = 0ull;   // tags 0 (first tag 1)
    __syncthreads();
    // zeroed slots visible cluster-wide before any remote store can land
    asm volatile("barrier.cluster.arrive.aligned;" ::: "memory");
    asm volatile("barrier.cluster.wait.aligned;"   ::: "memory");

    const uint32_t pbt0 = smem_u32(&pbt[0][0]);
    uint32_t peer_pbt;
    asm("mapa.shared::cluster.u32 %0, %1, %2;"
        : "=r"(peer_pbt) : "r"(pbt0), "r"(rank ^ 1));
    const uint32_t my_slot   = pbt0 + (uint32_t)jl * 8u;     // + buf*1024
    const uint32_t peer_slot = peer_pbt + (uint32_t)jl * 8u;

    const float* xpb = xp + (size_t)batch * T_ * H_;
    float*       ysb = ys + (size_t)batch * T_ * H_;

    float x_cur = 0.0f, x_next = 0.0f;
    if (mine && kq == 0) x_cur = __ldg(xpb + j);     // xp[t=0][j]

    for (int t = 0; t < T_; t++) {
        const uint32_t buf = (uint32_t)(t & 1);
        // --- 64-wide dot over this thread's k-quarter: 8 chains ----------
        const ulonglong2* hv = (const ulonglong2*)&hs[buf][kq][0];
        unsigned long long a0=0ull,a1=0ull,a2=0ull,a3=0ull,
                           a4=0ull,a5=0ull,a6=0ull,a7=0ull;
#pragma unroll
        for (int i = 0; i < 4; i++) {
            ulonglong2 p = hv[4*i];
            ulonglong2 q = hv[4*i + 1];
            ulonglong2 r = hv[4*i + 2];
            ulonglong2 u = hv[4*i + 3];
            a0 = ffma2(w[8*i+0], p.x, a0);
            a1 = ffma2(w[8*i+1], p.y, a1);
            a2 = ffma2(w[8*i+2], q.x, a2);
            a3 = ffma2(w[8*i+3], q.y, a3);
            a4 = ffma2(w[8*i+4], r.x, a4);
            a5 = ffma2(w[8*i+5], r.y, a5);
            a6 = ffma2(w[8*i+6], u.x, a6);
            a7 = ffma2(w[8*i+7], u.y, a7);
        }
        float2 f0=unpack2(a0), f1=unpack2(a1), f2=unpack2(a2), f3=unpack2(a3);
        float2 f4=unpack2(a4), f5=unpack2(a5), f6=unpack2(a6), f7=unpack2(a7);
        float s = (((f0.x+f0.y)+(f1.x+f1.y)) + ((f2.x+f2.y)+(f3.x+f3.y))) +
                  (((f4.x+f4.y)+(f5.x+f5.y)) + ((f6.x+f6.y)+(f7.x+f7.y)));
        // Combine the two k-quarters (lanes 2l, 2l+1 -> both hold tot)
        float tot = s + __shfl_xor_sync(0xFFFFFFFFu, s, 1);

        if (!mine) {
            if (kq == 0) {
                // One weak 8B store: (partial, tag=t+1). Single-copy atomic.
                unsigned long long msg;
                asm("mov.b64 %0, {%1, %2};"
                    : "=l"(msg)
                    : "r"(__float_as_uint(tot)), "r"((uint32_t)(t + 1)));
                asm volatile("st.shared::cluster.b64 [%0], %1;"
                             :: "r"(peer_slot + buf * 1024u), "l"(msg)
                             : "memory");
            }
        } else if (kq == 0) {
            if (t + 1 < T_)
                x_next = __ldg(xpb + (size_t)(t + 1) * H_ + j);
            // Spin until this step's tag shows up (value rides along).
            uint32_t lo, hi;
            const uint32_t addr = my_slot + buf * 1024u;
            const uint32_t want = (uint32_t)(t + 1);
            do {
                asm volatile("ld.volatile.shared.v2.u32 {%0, %1}, [%2];"
                             : "=r"(lo), "=r"(hi) : "r"(addr) : "memory");
            } while (hi != want);
            float v = tanh_fast(tot + __uint_as_float(lo) + x_cur);
            ysb[(size_t)t * H_ + j] = v;
            if (t + 1 < T_) hs[buf ^ 1u][jl >> 6][jl & 63] = v;
            x_cur = x_next;
        }
        __syncthreads();   // h[t+1] visible; orders slot reuse (WAR fence)
    }
}

// ---------------------------------------------------------------------------
// Launch: gemm0 -> scan0 -> gemm1 -> scan1 (all on the capture stream)
// ---------------------------------------------------------------------------
extern "C" void kernel_launch(void* const* d_in, const int* in_sizes, int n_in,
                              void* d_out, int out_size)
{
    const float* x     = (const float*)d_in[0];
    const float* W_ih0 = (const float*)d_in[1];
    const float* b_ih0 = (const float*)d_in[2];
    const float* W_hh0 = (const float*)d_in[3];
    const float* W_ih1 = (const float*)d_in[4];
    const float* b_ih1 = (const float*)d_in[5];
    const float* W_hh1 = (const float*)d_in[6];
    float* out = (float*)d_out;

    float *xp, *h;
    cudaGetSymbolAddress((void**)&xp, g_xp);
    cudaGetSymbolAddress((void**)&h,  g_h);

    dim3 ggrid(M_ / 128, H_ / 64);   // (512, 4)

    gemm_bias<<<ggrid, 256>>>(x, W_ih0, b_ih0, xp);
    elman_scan<<<B_ * 2, 512>>>(xp, W_hh0, h);
    gemm_bias<<<ggrid, 256>>>(h, W_ih1, b_ih1, xp);
    elman_scan<<<B_ * 2, 512>>>(xp, W_hh1, out);
}